// round 14
// baseline (speedup 1.0000x reference)
#include <cuda_runtime.h>
#include <cuda_bf16.h>
#include <cstdint>

// Problem: q,k,v [B=2,H=16,C=128,L=2048] fp32, L contiguous.
// weights = softmax over the q axis:
//   r[k]   = sum_q exp(S[q,k]),  S = Q^T K
//   O[c,q] = sum_k (V[c,k]/r[k]) * exp(S[q,k])
// Engine: mma.sync.m16n8k16 bf16. Precision: hi/lo bf16 split, 3-pass.
// R14: gemm2 rebuilt with 4-deep cp.async pipeline (16-deep k-chunks,
//      4 buffers, CP_WAIT(3)) to cover load latency; gemm1/preps = R13.
#define BH 32
#define CD 128
#define LL 2048

// ---------------- scratch (device globals; allocation is banned) ----------
__device__ __nv_bfloat16 g_Qh[(size_t)BH * LL * CD];  // [bh][q][c]
__device__ __nv_bfloat16 g_Ql[(size_t)BH * LL * CD];
__device__ __nv_bfloat16 g_Kh[(size_t)BH * LL * CD];  // [bh][k][c]
__device__ __nv_bfloat16 g_Kl[(size_t)BH * LL * CD];
__device__ __nv_bfloat16 g_Vh[(size_t)BH * CD * LL];  // [bh][c][k] (V/r)
__device__ __nv_bfloat16 g_Vl[(size_t)BH * CD * LL];
__device__ __nv_bfloat16 g_Eh[(size_t)BH * LL * LL];  // [bh][q][k]
__device__ __nv_bfloat16 g_El[(size_t)BH * LL * LL];
__device__ float         g_r[BH * LL];

// ---------------- smem geometry (gemm1, R13 layout) ------------------------
#define TSTR   80                 // bytes/row in 32-col bf16 tiles (odd 16B)
#define TILE_B (128 * TSTR)       // 10240
#define BUF_B  (4 * TILE_B)       // 40960 : Ah | Al | Bh | Bl
#define OFF_AH 0
#define OFF_AL TILE_B
#define OFF_BH (2 * TILE_B)
#define OFF_BL (3 * TILE_B)
#define OFF_CS (2 * BUF_B)        // 81920
#define SMEM_SZ (OFF_CS + 512)    // 82432 -> 2 CTAs/SM
#define ESTR   272                // staging row stride bytes (68 u32, odd 16B)

// ---------------- gemm2 v2 geometry: 16-deep chunks, 4 buffers -------------
#define T2STR  48                 // bytes/row in 16-col bf16 tiles (odd 16B)
#define TILE2  (128 * T2STR)      // 6144
#define BUF2   (4 * TILE2)        // 24576 : Ah | Al | Bh | Bl
#define O2_AH  0
#define O2_AL  TILE2
#define O2_BH  (2 * TILE2)
#define O2_BL  (3 * TILE2)
#define G2_SMEM (4 * BUF2 + 512)  // 98816 -> 2 CTAs/SM

// ---------------- ptx helpers ---------------------------------------------
__device__ __forceinline__ uint32_t smem_u32(const void* p) {
    uint32_t a;
    asm("{ .reg .u64 t; cvta.to.shared.u64 t, %1; cvt.u32.u64 %0, t; }"
        : "=r"(a) : "l"(p));
    return a;
}
__device__ __forceinline__ void cpa(uint32_t d, const void* s) {
    asm volatile("cp.async.cg.shared.global [%0], [%1], 16;"
                 :: "r"(d), "l"(__cvta_generic_to_global(s)));
}
#define CP_COMMIT() asm volatile("cp.async.commit_group;" ::: "memory")
#define CP_WAIT(n)  asm volatile("cp.async.wait_group %0;" :: "n"(n) : "memory")

__device__ __forceinline__ void ldsm4(uint32_t* r, uint32_t a) {
    asm volatile("ldmatrix.sync.aligned.m8n8.x4.shared.b16 {%0,%1,%2,%3}, [%4];"
                 : "=r"(r[0]), "=r"(r[1]), "=r"(r[2]), "=r"(r[3]) : "r"(a));
}
__device__ __forceinline__ void mma16816(float* d, const uint32_t* a, const uint32_t* b) {
    asm volatile("mma.sync.aligned.m16n8k16.row.col.f32.bf16.bf16.f32 "
                 "{%0,%1,%2,%3}, {%4,%5,%6,%7}, {%8,%9}, {%0,%1,%2,%3};"
                 : "+f"(d[0]), "+f"(d[1]), "+f"(d[2]), "+f"(d[3])
                 : "r"(a[0]), "r"(a[1]), "r"(a[2]), "r"(a[3]),
                   "r"(b[0]), "r"(b[1]));
}
// pack {bf16(a)<<16 | bf16(b)} : low half = bf16(b)
__device__ __forceinline__ uint32_t cvt2(float a, float b) {
    uint32_t d;
    asm("cvt.rn.bf16x2.f32 %0, %1, %2;" : "=r"(d) : "f"(a), "f"(b));
    return d;
}

// gemm1 loader: one 4-tile 32-deep chunk via cp.async
__device__ __forceinline__ void load_chunk(
    uint32_t buf, const __nv_bfloat16* ah, const __nv_bfloat16* al,
    const __nv_bfloat16* bh, const __nv_bfloat16* bl,
    int strideA, int strideB, int tid)
{
#pragma unroll
    for (int r = 0; r < 2; r++) {
        int idx = tid + 256 * r;       // 0..511
        int row = idx >> 2, seg = idx & 3;
        uint32_t d = buf + row * TSTR + seg * 16;
        size_t sa = (size_t)row * strideA + seg * 8;
        size_t sb = (size_t)row * strideB + seg * 8;
        cpa(d + OFF_AH, ah + sa);
        cpa(d + OFF_AL, al + sa);
        cpa(d + OFF_BH, bh + sb);
        cpa(d + OFF_BL, bl + sb);
    }
}

// gemm1 mma: one 32-deep chunk of 3-pass split mma: Ah*Bh + Ah*Bl + Al*Bh
__device__ __forceinline__ void mma_chunk(
    float acc[4][4][4], uint32_t buf, int wm, int wn, int lane)
{
    uint32_t a_base = buf + (uint32_t)(wm * 64 + (lane & 15)) * TSTR + ((lane >> 4) << 4);
    uint32_t b_base = buf + (uint32_t)(wn * 32 + ((lane >> 4) << 3) + (lane & 7)) * TSTR
                    + (((lane >> 3) & 1) << 4);
#pragma unroll
    for (int ks = 0; ks < 2; ks++) {
        uint32_t ah[4][4], al[4][4], bhf[4][2], blf[4][2];
#pragma unroll
        for (int i = 0; i < 4; i++) {
            ldsm4(ah[i], a_base + OFF_AH + i * 16 * TSTR + ks * 32);
            ldsm4(al[i], a_base + OFF_AL + i * 16 * TSTR + ks * 32);
        }
#pragma unroll
        for (int jj = 0; jj < 2; jj++) {
            uint32_t t[4];
            ldsm4(t, b_base + OFF_BH + jj * 16 * TSTR + ks * 32);
            bhf[2 * jj][0] = t[0]; bhf[2 * jj][1] = t[1];
            bhf[2 * jj + 1][0] = t[2]; bhf[2 * jj + 1][1] = t[3];
            ldsm4(t, b_base + OFF_BL + jj * 16 * TSTR + ks * 32);
            blf[2 * jj][0] = t[0]; blf[2 * jj][1] = t[1];
            blf[2 * jj + 1][0] = t[2]; blf[2 * jj + 1][1] = t[3];
        }
#pragma unroll
        for (int i = 0; i < 4; i++)
#pragma unroll
            for (int j = 0; j < 4; j++) {
                mma16816(acc[i][j], ah[i], bhf[j]);
                mma16816(acc[i][j], ah[i], blf[j]);
                mma16816(acc[i][j], al[i], bhf[j]);
            }
    }
}

// ---------------------------------------------------------------------------
// splitT v2: X [bh][c][l] f32 -> (Xh,Xl) [bh][l][c] bf16, 64-c x 32-l tiles,
// packed u32 stores; also zeroes g_r. grid (LL/32, CD/64, 2*BH), block (32,8)
// ---------------------------------------------------------------------------
__global__ void splitT_kernel(const float* __restrict__ Q,
                              const float* __restrict__ K) {
    __shared__ float tbuf[64][33];
    int z = blockIdx.z;
    int sel = z >= BH, bh = z & (BH - 1);
    int c0 = blockIdx.y * 64, l0 = blockIdx.x * 32;
    int tx = threadIdx.x, ty = threadIdx.y;
    const float* Xb = (sel ? K : Q) + ((size_t)bh * CD + c0) * LL + l0;
#pragma unroll
    for (int i = 0; i < 8; i++)
        tbuf[ty + 8 * i][tx] = Xb[(size_t)(ty + 8 * i) * LL + tx];

    if (!sel && blockIdx.y == 0 && ty == 0) g_r[bh * LL + l0 + tx] = 0.0f;
    __syncthreads();

    uint32_t* Dh = (uint32_t*)((sel ? g_Kh : g_Qh)
                   + ((size_t)bh * LL + l0) * CD + c0);
    uint32_t* Dl = (uint32_t*)((sel ? g_Kl : g_Ql)
                   + ((size_t)bh * LL + l0) * CD + c0);
#pragma unroll
    for (int i = 0; i < 4; i++) {
        int row = ty + 8 * i;
        float a = tbuf[2 * tx][row];
        float b = tbuf[2 * tx + 1][row];
        uint32_t h = cvt2(b, a);
        float fa = __uint_as_float(h << 16);
        float fb = __uint_as_float(h & 0xFFFF0000u);
        uint32_t l = cvt2(b - fb, a - fa);
        Dh[(size_t)row * (CD / 2) + tx] = h;
        Dl[(size_t)row * (CD / 2) + tx] = l;
    }
}

// Vr = V / r -> bf16 hi/lo (rinv folded in). grid (CD, BH), 256 threads.
__global__ void vprep_kernel(const float* __restrict__ V) {
    int c = blockIdx.x, bh = blockIdx.y;
    size_t base = ((size_t)bh * CD + c) * LL;
    const float4* v4 = (const float4*)(V + base);
    const float4* r4 = (const float4*)(g_r + bh * LL);
    uint32_t* dh = (uint32_t*)(g_Vh + base);
    uint32_t* dl = (uint32_t*)(g_Vl + base);
    int t = threadIdx.x;
#pragma unroll
    for (int it = 0; it < 2; it++) {
        int i = t + 256 * it;
        float4 v = v4[i], r = r4[i];
        float a0 = __fdividef(v.x, r.x), a1 = __fdividef(v.y, r.y);
        float a2 = __fdividef(v.z, r.z), a3 = __fdividef(v.w, r.w);
        uint32_t h01 = cvt2(a1, a0), h23 = cvt2(a3, a2);
        float f0 = __uint_as_float(h01 << 16);
        float f1 = __uint_as_float(h01 & 0xFFFF0000u);
        float f2 = __uint_as_float(h23 << 16);
        float f3 = __uint_as_float(h23 & 0xFFFF0000u);
        uint32_t l01 = cvt2(a1 - f1, a0 - f0);
        uint32_t l23 = cvt2(a3 - f3, a2 - f2);
        dh[2 * i]     = h01;
        dh[2 * i + 1] = h23;
        dl[2 * i]     = l01;
        dl[2 * i + 1] = l23;
    }
}

// ---------------------------------------------------------------------------
// GEMM1 (R13, unchanged): S tile [128q x 128k], exp epilogue, colsum,
// staged split-store. grid (16, 16, 32), 256 threads, 2 CTAs/SM.
// ---------------------------------------------------------------------------
__global__ __launch_bounds__(256, 2) void gemm1_kernel() {
    extern __shared__ char sm[];
    const uint32_t sb = smem_u32(sm);
    const int tid = threadIdx.x, wid = tid >> 5, lane = tid & 31;
    const int wm = wid & 1, wn = wid >> 1;
    const int q0 = blockIdx.x * 128, k0 = blockIdx.y * 128, bh = blockIdx.z;

    {
        int flat = blockIdx.x + 16 * (blockIdx.y + 16 * blockIdx.z);
        if (flat >= 148 && flat < 296) {
            long long t0 = clock64();
            while (clock64() - t0 < 11000) {}
        }
    }

    float* cs = (float*)(sm + OFF_CS);
    if (tid < 128) cs[tid] = 0.0f;

    const __nv_bfloat16* Qh = g_Qh + ((size_t)bh * LL + q0) * CD;
    const __nv_bfloat16* Ql = g_Ql + ((size_t)bh * LL + q0) * CD;
    const __nv_bfloat16* Kh = g_Kh + ((size_t)bh * LL + k0) * CD;
    const __nv_bfloat16* Kl = g_Kl + ((size_t)bh * LL + k0) * CD;

    load_chunk(sb, Qh, Ql, Kh, Kl, CD, CD, tid);
    CP_COMMIT();

    float acc[4][4][4];
#pragma unroll
    for (int i = 0; i < 4; i++)
#pragma unroll
        for (int j = 0; j < 4; j++)
#pragma unroll
            for (int v = 0; v < 4; v++) acc[i][j][v] = 0.0f;

#pragma unroll 1
    for (int ck = 0; ck < 4; ck++) {
        CP_WAIT(0);
        __syncthreads();
        if (ck + 1 < 4) {
            int off = (ck + 1) * 32;
            load_chunk(sb + ((ck + 1) & 1) * BUF_B, Qh + off, Ql + off,
                       Kh + off, Kl + off, CD, CD, tid);
            CP_COMMIT();
        }
        mma_chunk(acc, sb + (ck & 1) * BUF_B, wm, wn, lane);
    }
    __syncthreads();

#pragma unroll
    for (int i = 0; i < 4; i++)
#pragma unroll
        for (int j = 0; j < 4; j++)
#pragma unroll
            for (int v = 0; v < 4; v++) acc[i][j][v] = __expf(acc[i][j][v]);

#pragma unroll
    for (int j = 0; j < 4; j++) {
        float p0 = 0.0f, p1 = 0.0f;
#pragma unroll
        for (int i = 0; i < 4; i++) {
            p0 += acc[i][j][0] + acc[i][j][2];
            p1 += acc[i][j][1] + acc[i][j][3];
        }
        p0 += __shfl_xor_sync(0xffffffffu, p0, 4);
        p1 += __shfl_xor_sync(0xffffffffu, p1, 4);
        p0 += __shfl_xor_sync(0xffffffffu, p0, 8);
        p1 += __shfl_xor_sync(0xffffffffu, p1, 8);
        p0 += __shfl_xor_sync(0xffffffffu, p0, 16);
        p1 += __shfl_xor_sync(0xffffffffu, p1, 16);
        if ((lane >> 2) == 0) {
            int c = wn * 32 + j * 8 + (lane & 3) * 2;
            atomicAdd(&cs[c], p0);
            atomicAdd(&cs[c + 1], p1);
        }
    }

    uint32_t* stH = (uint32_t*)(sm);
    uint32_t* stL = (uint32_t*)(sm + 128 * ESTR);
#pragma unroll
    for (int i = 0; i < 4; i++)
#pragma unroll
        for (int j = 0; j < 4; j++) {
            int r  = wm * 64 + i * 16 + (lane >> 2);
            int cu = wn * 16 + j * 4 + (lane & 3);
            float a0 = acc[i][j][0], a1 = acc[i][j][1];
            float a2 = acc[i][j][2], a3 = acc[i][j][3];
            uint32_t hp01 = cvt2(a1, a0);
            uint32_t hp23 = cvt2(a3, a2);
            float f0 = __uint_as_float(hp01 << 16);
            float f1 = __uint_as_float(hp01 & 0xFFFF0000u);
            float f2 = __uint_as_float(hp23 << 16);
            float f3 = __uint_as_float(hp23 & 0xFFFF0000u);
            uint32_t lp01 = cvt2(a1 - f1, a0 - f0);
            uint32_t lp23 = cvt2(a3 - f3, a2 - f2);
            stH[r * 68 + cu]       = hp01;
            stH[(r + 8) * 68 + cu] = hp23;
            stL[r * 68 + cu]       = lp01;
            stL[(r + 8) * 68 + cu] = lp23;
        }
    __syncthreads();

    if (tid < 128) atomicAdd(&g_r[bh * LL + k0 + tid], cs[tid]);

    __nv_bfloat16* EhD = g_Eh + ((size_t)bh * LL + q0) * LL + k0;
    __nv_bfloat16* ElD = g_El + ((size_t)bh * LL + q0) * LL + k0;
#pragma unroll
    for (int r8 = 0; r8 < 8; r8++) {
        int idx = tid + 256 * r8;
        int row = idx >> 4, seg = idx & 15;
        *(uint4*)(EhD + (size_t)row * LL + seg * 8) =
            *(const uint4*)((const char*)sm + row * ESTR + seg * 16);
        *(uint4*)(ElD + (size_t)row * LL + seg * 8) =
            *(const uint4*)((const char*)sm + 128 * ESTR + row * ESTR + seg * 16);
    }
}

// ---------------------------------------------------------------------------
// GEMM2 v2: O[c,q] = sum_k Vr[c,k]*E[q,k]; 128 k-chunks of 16, 4 smem
// buffers, prefetch distance 3 (CP_WAIT(3), one commit per iteration).
// grid (16 qt, 32 bh), 256 threads, 2 CTAs/SM
// ---------------------------------------------------------------------------
__device__ __forceinline__ void g2_load16(
    uint32_t buf, const __nv_bfloat16* ah, const __nv_bfloat16* al,
    const __nv_bfloat16* bh, const __nv_bfloat16* bl, int tid)
{
    int row = tid >> 1, seg = tid & 1;       // 128 rows x 2 segs = 256
    uint32_t d = buf + row * T2STR + seg * 16;
    size_t s = (size_t)row * LL + seg * 8;
    cpa(d + O2_AH, ah + s);
    cpa(d + O2_AL, al + s);
    cpa(d + O2_BH, bh + s);
    cpa(d + O2_BL, bl + s);
}

__device__ __forceinline__ void mma_chunk16(
    float acc[4][4][4], uint32_t buf, int wm, int wn, int lane)
{
    uint32_t a_base = buf + (uint32_t)(wm * 64 + (lane & 15)) * T2STR + ((lane >> 4) << 4);
    uint32_t b_base = buf + (uint32_t)(wn * 32 + ((lane >> 4) << 3) + (lane & 7)) * T2STR
                    + (((lane >> 3) & 1) << 4);
    uint32_t ah[4][4], al[4][4], bhf[4][2], blf[4][2];
#pragma unroll
    for (int i = 0; i < 4; i++) {
        ldsm4(ah[i], a_base + O2_AH + i * 16 * T2STR);
        ldsm4(al[i], a_base + O2_AL + i * 16 * T2STR);
    }
#pragma unroll
    for (int jj = 0; jj < 2; jj++) {
        uint32_t t[4];
        ldsm4(t, b_base + O2_BH + jj * 16 * T2STR);
        bhf[2 * jj][0] = t[0]; bhf[2 * jj][1] = t[1];
        bhf[2 * jj + 1][0] = t[2]; bhf[2 * jj + 1][1] = t[3];
        ldsm4(t, b_base + O2_BL + jj * 16 * T2STR);
        blf[2 * jj][0] = t[0]; blf[2 * jj][1] = t[1];
        blf[2 * jj + 1][0] = t[2]; blf[2 * jj + 1][1] = t[3];
    }
#pragma unroll
    for (int i = 0; i < 4; i++)
#pragma unroll
        for (int j = 0; j < 4; j++) {
            mma16816(acc[i][j], ah[i], bhf[j]);
            mma16816(acc[i][j], ah[i], blf[j]);
            mma16816(acc[i][j], al[i], bhf[j]);
        }
}

__global__ __launch_bounds__(256, 2) void gemm2_kernel(float* __restrict__ Out) {
    extern __shared__ char sm[];
    const uint32_t sb = smem_u32(sm);
    const int tid = threadIdx.x, wid = tid >> 5, lane = tid & 31;
    const int wm = wid & 1, wn = wid >> 1;
    const int q0 = blockIdx.x * 128, bh = blockIdx.y;

    const __nv_bfloat16* Vh = g_Vh + (size_t)bh * CD * LL;
    const __nv_bfloat16* Vl = g_Vl + (size_t)bh * CD * LL;
    const __nv_bfloat16* Eh = g_Eh + ((size_t)bh * LL + q0) * LL;
    const __nv_bfloat16* El = g_El + ((size_t)bh * LL + q0) * LL;

    // preload chunks 0..2, one commit group each
#pragma unroll
    for (int p = 0; p < 3; p++) {
        int off = p * 16;
        g2_load16(sb + p * BUF2, Vh + off, Vl + off, Eh + off, El + off, tid);
        CP_COMMIT();
    }

    float acc[4][4][4];
#pragma unroll
    for (int i = 0; i < 4; i++)
#pragma unroll
        for (int j = 0; j < 4; j++)
#pragma unroll
            for (int v = 0; v < 4; v++) acc[i][j][v] = 0.0f;

#pragma unroll 1
    for (int ck = 0; ck < 128; ck++) {
        __syncthreads();               // mma(ck-1) done everywhere
        if (ck + 3 < 128) {            // load into buffer mma(ck-1) vacated
            int off = (ck + 3) * 16;
            g2_load16(sb + ((ck + 3) & 3) * BUF2,
                      Vh + off, Vl + off, Eh + off, El + off, tid);
        }
        CP_COMMIT();                   // always commit (may be empty group)
        CP_WAIT(3);                    // chunk ck fully arrived
        mma_chunk16(acc, sb + (ck & 3) * BUF2, wm, wn, lane);
    }

    // epilogue: direct f32 stores, Out [bh][c][q]
#pragma unroll
    for (int i = 0; i < 4; i++)
#pragma unroll
        for (int j = 0; j < 4; j++) {
            int r  = wm * 64 + i * 16 + (lane >> 2);
            int qc = q0 + wn * 32 + j * 8 + (lane & 3) * 2;
            float* ob = Out + ((size_t)bh * CD + r) * LL + qc;
            *(float2*)ob = make_float2(acc[i][j][0], acc[i][j][1]);
            *(float2*)(ob + 8 * LL) = make_float2(acc[i][j][2], acc[i][j][3]);
        }
}

// ---------------------------------------------------------------------------
extern "C" void kernel_launch(void* const* d_in, const int* in_sizes, int n_in,
                              void* d_out, int out_size)
{
    const float* q = (const float*)d_in[0];
    const float* k = (const float*)d_in[1];
    const float* v = (const float*)d_in[2];
    float* out = (float*)d_out;

    cudaFuncSetAttribute(gemm1_kernel, cudaFuncAttributeMaxDynamicSharedMemorySize, SMEM_SZ);
    cudaFuncSetAttribute(gemm2_kernel, cudaFuncAttributeMaxDynamicSharedMemorySize, G2_SMEM);

    splitT_kernel<<<dim3(LL / 32, CD / 64, 2 * BH), dim3(32, 8)>>>(q, k);
    gemm1_kernel<<<dim3(16, 16, BH), 256, SMEM_SZ>>>();
    vprep_kernel<<<dim3(CD, BH), 256>>>(v);
    gemm2_kernel<<<dim3(16, BH), 256, G2_SMEM>>>(out);
}

// round 16
// speedup vs baseline: 1.0817x; 1.0817x over previous
#include <cuda_runtime.h>
#include <cuda_bf16.h>
#include <cstdint>

// Problem: q,k,v [B=2,H=16,C=128,L=2048] fp32, L contiguous.
// weights = softmax over the q axis:
//   r[k]   = sum_q exp(S[q,k]),  S = Q^T K
//   O[c,q] = sum_k (V[c,k]/r[k]) * exp(S[q,k])
// Engine: mma.sync.m16n8k16 bf16. Precision: hi/lo bf16 split, 3-pass.
// R16: recovery — exact R13 configuration (best known, 752.0us) with one
//      zero-risk tweak (unroll-2 on gemm2's chunk loop). R15's bulk-copy
//      rewrite was emitted truncated and never actually ran.
#define BH 32
#define CD 128
#define LL 2048

// ---------------- scratch (device globals; allocation is banned) ----------
__device__ __nv_bfloat16 g_Qh[(size_t)BH * LL * CD];  // [bh][q][c]
__device__ __nv_bfloat16 g_Ql[(size_t)BH * LL * CD];
__device__ __nv_bfloat16 g_Kh[(size_t)BH * LL * CD];  // [bh][k][c]
__device__ __nv_bfloat16 g_Kl[(size_t)BH * LL * CD];
__device__ __nv_bfloat16 g_Vh[(size_t)BH * CD * LL];  // [bh][c][k] (V/r)
__device__ __nv_bfloat16 g_Vl[(size_t)BH * CD * LL];
__device__ __nv_bfloat16 g_Eh[(size_t)BH * LL * LL];  // [bh][q][k]
__device__ __nv_bfloat16 g_El[(size_t)BH * LL * LL];
__device__ float         g_r[BH * LL];

// ---------------- smem geometry -------------------------------------------
#define TSTR   80                 // bytes/row in 32-col bf16 tiles (odd 16B)
#define TILE_B (128 * TSTR)       // 10240
#define BUF_B  (4 * TILE_B)       // 40960 : Ah | Al | Bh | Bl
#define OFF_AH 0
#define OFF_AL TILE_B
#define OFF_BH (2 * TILE_B)
#define OFF_BL (3 * TILE_B)
#define OFF_CS (2 * BUF_B)        // 81920
#define SMEM_SZ (OFF_CS + 512)    // 82432 -> 2 CTAs/SM
#define ESTR   272                // staging row stride bytes (68 u32, odd 16B)

// ---------------- ptx helpers ---------------------------------------------
__device__ __forceinline__ uint32_t smem_u32(const void* p) {
    uint32_t a;
    asm("{ .reg .u64 t; cvta.to.shared.u64 t, %1; cvt.u32.u64 %0, t; }"
        : "=r"(a) : "l"(p));
    return a;
}
__device__ __forceinline__ void cpa(uint32_t d, const void* s) {
    asm volatile("cp.async.cg.shared.global [%0], [%1], 16;"
                 :: "r"(d), "l"(__cvta_generic_to_global(s)));
}
#define CP_COMMIT() asm volatile("cp.async.commit_group;" ::: "memory")
#define CP_WAIT(n)  asm volatile("cp.async.wait_group %0;" :: "n"(n) : "memory")

__device__ __forceinline__ void ldsm4(uint32_t* r, uint32_t a) {
    asm volatile("ldmatrix.sync.aligned.m8n8.x4.shared.b16 {%0,%1,%2,%3}, [%4];"
                 : "=r"(r[0]), "=r"(r[1]), "=r"(r[2]), "=r"(r[3]) : "r"(a));
}
__device__ __forceinline__ void mma16816(float* d, const uint32_t* a, const uint32_t* b) {
    asm volatile("mma.sync.aligned.m16n8k16.row.col.f32.bf16.bf16.f32 "
                 "{%0,%1,%2,%3}, {%4,%5,%6,%7}, {%8,%9}, {%0,%1,%2,%3};"
                 : "+f"(d[0]), "+f"(d[1]), "+f"(d[2]), "+f"(d[3])
                 : "r"(a[0]), "r"(a[1]), "r"(a[2]), "r"(a[3]),
                   "r"(b[0]), "r"(b[1]));
}
// pack {bf16(a)<<16 | bf16(b)} : low half = bf16(b)
__device__ __forceinline__ uint32_t cvt2(float a, float b) {
    uint32_t d;
    asm("cvt.rn.bf16x2.f32 %0, %1, %2;" : "=r"(d) : "f"(a), "f"(b));
    return d;
}

// load one 4-tile k-chunk (Ah,Al,Bh,Bl: 128 rows x 32 bf16 each) via cp.async
__device__ __forceinline__ void load_chunk(
    uint32_t buf, const __nv_bfloat16* ah, const __nv_bfloat16* al,
    const __nv_bfloat16* bh, const __nv_bfloat16* bl,
    int strideA, int strideB, int tid)
{
#pragma unroll
    for (int r = 0; r < 2; r++) {
        int idx = tid + 256 * r;       // 0..511
        int row = idx >> 2, seg = idx & 3;
        uint32_t d = buf + row * TSTR + seg * 16;
        size_t sa = (size_t)row * strideA + seg * 8;
        size_t sb = (size_t)row * strideB + seg * 8;
        cpa(d + OFF_AH, ah + sa);
        cpa(d + OFF_AL, al + sa);
        cpa(d + OFF_BH, bh + sb);
        cpa(d + OFF_BL, bl + sb);
    }
}

// one 32-deep k-chunk of 3-pass split mma: acc += Ah*Bh + Ah*Bl + Al*Bh
__device__ __forceinline__ void mma_chunk(
    float acc[4][4][4], uint32_t buf, int wm, int wn, int lane)
{
    uint32_t a_base = buf + (uint32_t)(wm * 64 + (lane & 15)) * TSTR + ((lane >> 4) << 4);
    uint32_t b_base = buf + (uint32_t)(wn * 32 + ((lane >> 4) << 3) + (lane & 7)) * TSTR
                    + (((lane >> 3) & 1) << 4);
#pragma unroll
    for (int ks = 0; ks < 2; ks++) {
        uint32_t ah[4][4], al[4][4], bhf[4][2], blf[4][2];
#pragma unroll
        for (int i = 0; i < 4; i++) {
            ldsm4(ah[i], a_base + OFF_AH + i * 16 * TSTR + ks * 32);
            ldsm4(al[i], a_base + OFF_AL + i * 16 * TSTR + ks * 32);
        }
#pragma unroll
        for (int jj = 0; jj < 2; jj++) {
            uint32_t t[4];
            ldsm4(t, b_base + OFF_BH + jj * 16 * TSTR + ks * 32);
            bhf[2 * jj][0] = t[0]; bhf[2 * jj][1] = t[1];
            bhf[2 * jj + 1][0] = t[2]; bhf[2 * jj + 1][1] = t[3];
            ldsm4(t, b_base + OFF_BL + jj * 16 * TSTR + ks * 32);
            blf[2 * jj][0] = t[0]; blf[2 * jj][1] = t[1];
            blf[2 * jj + 1][0] = t[2]; blf[2 * jj + 1][1] = t[3];
        }
#pragma unroll
        for (int i = 0; i < 4; i++)
#pragma unroll
            for (int j = 0; j < 4; j++) {
                mma16816(acc[i][j], ah[i], bhf[j]);
                mma16816(acc[i][j], ah[i], blf[j]);
                mma16816(acc[i][j], al[i], bhf[j]);
            }
    }
}

// ---------------------------------------------------------------------------
// splitT v2: X [bh][c][l] f32 -> (Xh,Xl) [bh][l][c] bf16, 64-c x 32-l tiles,
// packed u32 stores; also zeroes g_r. grid (LL/32, CD/64, 2*BH), block (32,8)
// ---------------------------------------------------------------------------
__global__ void splitT_kernel(const float* __restrict__ Q,
                              const float* __restrict__ K) {
    __shared__ float tbuf[64][33];
    int z = blockIdx.z;
    int sel = z >= BH, bh = z & (BH - 1);
    int c0 = blockIdx.y * 64, l0 = blockIdx.x * 32;
    int tx = threadIdx.x, ty = threadIdx.y;
    const float* Xb = (sel ? K : Q) + ((size_t)bh * CD + c0) * LL + l0;
#pragma unroll
    for (int i = 0; i < 8; i++)
        tbuf[ty + 8 * i][tx] = Xb[(size_t)(ty + 8 * i) * LL + tx];

    if (!sel && blockIdx.y == 0 && ty == 0) g_r[bh * LL + l0 + tx] = 0.0f;
    __syncthreads();

    uint32_t* Dh = (uint32_t*)((sel ? g_Kh : g_Qh)
                   + ((size_t)bh * LL + l0) * CD + c0);
    uint32_t* Dl = (uint32_t*)((sel ? g_Kl : g_Ql)
                   + ((size_t)bh * LL + l0) * CD + c0);
#pragma unroll
    for (int i = 0; i < 4; i++) {
        int row = ty + 8 * i;
        float a = tbuf[2 * tx][row];
        float b = tbuf[2 * tx + 1][row];
        uint32_t h = cvt2(b, a);
        float fa = __uint_as_float(h << 16);
        float fb = __uint_as_float(h & 0xFFFF0000u);
        uint32_t l = cvt2(b - fb, a - fa);
        Dh[(size_t)row * (CD / 2) + tx] = h;
        Dl[(size_t)row * (CD / 2) + tx] = l;
    }
}

// Vr = V / r -> bf16 hi/lo (rinv folded in). grid (CD, BH), 256 threads.
__global__ void vprep_kernel(const float* __restrict__ V) {
    int c = blockIdx.x, bh = blockIdx.y;
    size_t base = ((size_t)bh * CD + c) * LL;
    const float4* v4 = (const float4*)(V + base);
    const float4* r4 = (const float4*)(g_r + bh * LL);
    uint32_t* dh = (uint32_t*)(g_Vh + base);
    uint32_t* dl = (uint32_t*)(g_Vl + base);
    int t = threadIdx.x;
#pragma unroll
    for (int it = 0; it < 2; it++) {
        int i = t + 256 * it;
        float4 v = v4[i], r = r4[i];
        float a0 = __fdividef(v.x, r.x), a1 = __fdividef(v.y, r.y);
        float a2 = __fdividef(v.z, r.z), a3 = __fdividef(v.w, r.w);
        uint32_t h01 = cvt2(a1, a0), h23 = cvt2(a3, a2);
        float f0 = __uint_as_float(h01 << 16);
        float f1 = __uint_as_float(h01 & 0xFFFF0000u);
        float f2 = __uint_as_float(h23 << 16);
        float f3 = __uint_as_float(h23 & 0xFFFF0000u);
        uint32_t l01 = cvt2(a1 - f1, a0 - f0);
        uint32_t l23 = cvt2(a3 - f3, a2 - f2);
        dh[2 * i]     = h01;
        dh[2 * i + 1] = h23;
        dl[2 * i]     = l01;
        dl[2 * i + 1] = l23;
    }
}

// ---------------------------------------------------------------------------
// GEMM1: S tile [128q x 128k] over c=128 (4 chunks of 32), exp epilogue,
//        colsum->g_r, split-store Eh/El via coalescing staging.
// grid (16 qt, 16 kt, 32 bh), 256 threads, 2 CTAs/SM
// ---------------------------------------------------------------------------
__global__ __launch_bounds__(256, 2) void gemm1_kernel() {
    extern __shared__ char sm[];
    const uint32_t sb = smem_u32(sm);
    const int tid = threadIdx.x, wid = tid >> 5, lane = tid & 31;
    const int wm = wid & 1, wn = wid >> 1;
    const int q0 = blockIdx.x * 128, k0 = blockIdx.y * 128, bh = blockIdx.z;

    // Phase-stagger: the second first-wave CTA on each SM delays ~11K cycles
    // (≈ epilogue length) so co-resident CTAs run epilogue-vs-mainloop.
    {
        int flat = blockIdx.x + 16 * (blockIdx.y + 16 * blockIdx.z);
        if (flat >= 148 && flat < 296) {
            long long t0 = clock64();
            while (clock64() - t0 < 11000) {}
        }
    }

    float* cs = (float*)(sm + OFF_CS);
    if (tid < 128) cs[tid] = 0.0f;

    const __nv_bfloat16* Qh = g_Qh + ((size_t)bh * LL + q0) * CD;
    const __nv_bfloat16* Ql = g_Ql + ((size_t)bh * LL + q0) * CD;
    const __nv_bfloat16* Kh = g_Kh + ((size_t)bh * LL + k0) * CD;
    const __nv_bfloat16* Kl = g_Kl + ((size_t)bh * LL + k0) * CD;

    load_chunk(sb, Qh, Ql, Kh, Kl, CD, CD, tid);
    CP_COMMIT();

    float acc[4][4][4];
#pragma unroll
    for (int i = 0; i < 4; i++)
#pragma unroll
        for (int j = 0; j < 4; j++)
#pragma unroll
            for (int v = 0; v < 4; v++) acc[i][j][v] = 0.0f;

#pragma unroll 1
    for (int ck = 0; ck < 4; ck++) {
        CP_WAIT(0);
        __syncthreads();
        if (ck + 1 < 4) {
            int off = (ck + 1) * 32;
            load_chunk(sb + ((ck + 1) & 1) * BUF_B, Qh + off, Ql + off,
                       Kh + off, Kl + off, CD, CD, tid);
            CP_COMMIT();
        }
        mma_chunk(acc, sb + (ck & 1) * BUF_B, wm, wn, lane);
    }
    __syncthreads();   // all warps done with buffers -> staging may reuse smem

    // exp in place + column sums
#pragma unroll
    for (int i = 0; i < 4; i++)
#pragma unroll
        for (int j = 0; j < 4; j++)
#pragma unroll
            for (int v = 0; v < 4; v++) acc[i][j][v] = __expf(acc[i][j][v]);

#pragma unroll
    for (int j = 0; j < 4; j++) {
        float p0 = 0.0f, p1 = 0.0f;
#pragma unroll
        for (int i = 0; i < 4; i++) {
            p0 += acc[i][j][0] + acc[i][j][2];
            p1 += acc[i][j][1] + acc[i][j][3];
        }
        p0 += __shfl_xor_sync(0xffffffffu, p0, 4);
        p1 += __shfl_xor_sync(0xffffffffu, p1, 4);
        p0 += __shfl_xor_sync(0xffffffffu, p0, 8);
        p1 += __shfl_xor_sync(0xffffffffu, p1, 8);
        p0 += __shfl_xor_sync(0xffffffffu, p0, 16);
        p1 += __shfl_xor_sync(0xffffffffu, p1, 16);
        if ((lane >> 2) == 0) {
            int c = wn * 32 + j * 8 + (lane & 3) * 2;
            atomicAdd(&cs[c], p0);
            atomicAdd(&cs[c + 1], p1);
        }
    }

    // stage hi/lo bf16x2 tiles (conflict-free 272B-row layout, reuses buffers)
    uint32_t* stH = (uint32_t*)(sm);
    uint32_t* stL = (uint32_t*)(sm + 128 * ESTR);
#pragma unroll
    for (int i = 0; i < 4; i++)
#pragma unroll
        for (int j = 0; j < 4; j++) {
            int r  = wm * 64 + i * 16 + (lane >> 2);
            int cu = wn * 16 + j * 4 + (lane & 3);
            float a0 = acc[i][j][0], a1 = acc[i][j][1];
            float a2 = acc[i][j][2], a3 = acc[i][j][3];
            uint32_t hp01 = cvt2(a1, a0);           // low = bf16(a0)
            uint32_t hp23 = cvt2(a3, a2);
            float f0 = __uint_as_float(hp01 << 16);
            float f1 = __uint_as_float(hp01 & 0xFFFF0000u);
            float f2 = __uint_as_float(hp23 << 16);
            float f3 = __uint_as_float(hp23 & 0xFFFF0000u);
            uint32_t lp01 = cvt2(a1 - f1, a0 - f0);
            uint32_t lp23 = cvt2(a3 - f3, a2 - f2);
            stH[r * 68 + cu]       = hp01;
            stH[(r + 8) * 68 + cu] = hp23;
            stL[r * 68 + cu]       = lp01;
            stL[(r + 8) * 68 + cu] = lp23;
        }
    __syncthreads();

    if (tid < 128) atomicAdd(&g_r[bh * LL + k0 + tid], cs[tid]);

    __nv_bfloat16* EhD = g_Eh + ((size_t)bh * LL + q0) * LL + k0;
    __nv_bfloat16* ElD = g_El + ((size_t)bh * LL + q0) * LL + k0;
#pragma unroll
    for (int r8 = 0; r8 < 8; r8++) {
        int idx = tid + 256 * r8;        // 0..2047
        int row = idx >> 4, seg = idx & 15;
        *(uint4*)(EhD + (size_t)row * LL + seg * 8) =
            *(const uint4*)((const char*)sm + row * ESTR + seg * 16);
        *(uint4*)(ElD + (size_t)row * LL + seg * 8) =
            *(const uint4*)((const char*)sm + 128 * ESTR + row * ESTR + seg * 16);
    }
}

// ---------------------------------------------------------------------------
// GEMM2: O[c,q] = sum_k Vr[c,k]*E[q,k]; 64 k-chunks of 32, double-buffered,
//        one barrier per chunk. grid (16 qt, 32 bh), 256 threads, 2 CTAs/SM
// ---------------------------------------------------------------------------
__global__ __launch_bounds__(256, 2) void gemm2_kernel(float* __restrict__ Out) {
    extern __shared__ char sm[];
    const uint32_t sb = smem_u32(sm);
    const int tid = threadIdx.x, wid = tid >> 5, lane = tid & 31;
    const int wm = wid & 1, wn = wid >> 1;
    const int q0 = blockIdx.x * 128, bh = blockIdx.y;

    const __nv_bfloat16* Vh = g_Vh + (size_t)bh * CD * LL;
    const __nv_bfloat16* Vl = g_Vl + (size_t)bh * CD * LL;
    const __nv_bfloat16* Eh = g_Eh + ((size_t)bh * LL + q0) * LL;
    const __nv_bfloat16* El = g_El + ((size_t)bh * LL + q0) * LL;

    load_chunk(sb, Vh, Vl, Eh, El, LL, LL, tid);
    CP_COMMIT();

    float acc[4][4][4];
#pragma unroll
    for (int i = 0; i < 4; i++)
#pragma unroll
        for (int j = 0; j < 4; j++)
#pragma unroll
            for (int v = 0; v < 4; v++) acc[i][j][v] = 0.0f;

#pragma unroll 2
    for (int ck = 0; ck < 64; ck++) {
        CP_WAIT(0);
        __syncthreads();
        if (ck + 1 < 64) {
            int off = (ck + 1) * 32;
            load_chunk(sb + ((ck + 1) & 1) * BUF_B, Vh + off, Vl + off,
                       Eh + off, El + off, LL, LL, tid);
            CP_COMMIT();
        }
        mma_chunk(acc, sb + (ck & 1) * BUF_B, wm, wn, lane);
    }

    // epilogue: direct f32 stores, Out [bh][c][q]
#pragma unroll
    for (int i = 0; i < 4; i++)
#pragma unroll
        for (int j = 0; j < 4; j++) {
            int r  = wm * 64 + i * 16 + (lane >> 2);
            int qc = q0 + wn * 32 + j * 8 + (lane & 3) * 2;
            float* ob = Out + ((size_t)bh * CD + r) * LL + qc;
            *(float2*)ob = make_float2(acc[i][j][0], acc[i][j][1]);
            *(float2*)(ob + 8 * LL) = make_float2(acc[i][j][2], acc[i][j][3]);
        }
}

// ---------------------------------------------------------------------------
extern "C" void kernel_launch(void* const* d_in, const int* in_sizes, int n_in,
                              void* d_out, int out_size)
{
    const float* q = (const float*)d_in[0];
    const float* k = (const float*)d_in[1];
    const float* v = (const float*)d_in[2];
    float* out = (float*)d_out;

    cudaFuncSetAttribute(gemm1_kernel, cudaFuncAttributeMaxDynamicSharedMemorySize, SMEM_SZ);
    cudaFuncSetAttribute(gemm2_kernel, cudaFuncAttributeMaxDynamicSharedMemorySize, SMEM_SZ);

    splitT_kernel<<<dim3(LL / 32, CD / 64, 2 * BH), dim3(32, 8)>>>(q, k);
    gemm1_kernel<<<dim3(16, 16, BH), 256, SMEM_SZ>>>();
    vprep_kernel<<<dim3(CD, BH), 256>>>(v);
    gemm2_kernel<<<dim3(16, BH), 256, SMEM_SZ>>>(out);
}

// round 17
// speedup vs baseline: 1.2100x; 1.1186x over previous
#include <cuda_runtime.h>
#include <cuda_bf16.h>
#include <cstdint>

// Problem: q,k,v [B=2,H=16,C=128,L=2048] fp32, L contiguous.
//   r[k] = sum_q exp(S[q,k]), S = Q^T K ; O[c,q] = sum_k (V[c,k]/r[k])E[q,k]
// Engine: mma.sync.m16n8k16 bf16, hi/lo split 3-pass.
// R17: V/E stored as pre-swizzled 8KB blocks (128 rows x 64B, XOR (row&14)<<3);
//      gemm2 loads each chunk with 4 cp.async.bulk + mbarrier (was 2560
//      cp.async.16B -> LDGSTS-issue bound); gemm1 E-store now contiguous.
#define BH 32
#define CD 128
#define LL 2048
#define BLK 8192

__device__ __nv_bfloat16 g_Qh[(size_t)BH * LL * CD];  // [bh][l][c] (splitT)
__device__ __nv_bfloat16 g_Ql[(size_t)BH * LL * CD];
__device__ __nv_bfloat16 g_Kh[(size_t)BH * LL * CD];
__device__ __nv_bfloat16 g_Kl[(size_t)BH * LL * CD];
__device__ __nv_bfloat16 g_Vh[(size_t)BH * CD * LL];  // blocks [bh][ck=64]
__device__ __nv_bfloat16 g_Vl[(size_t)BH * CD * LL];
__device__ __nv_bfloat16 g_Eh[(size_t)BH * LL * LL];  // blocks [bh][qb=16][ck=64]
__device__ __nv_bfloat16 g_El[(size_t)BH * LL * LL];
__device__ float         g_r[BH * LL];

// gemm1 geometry (R16)
#define TSTR   80
#define TILE_B (128 * TSTR)
#define BUF_B  (4 * TILE_B)
#define OFF_AH 0
#define OFF_AL TILE_B
#define OFF_BH (2 * TILE_B)
#define OFF_BL (3 * TILE_B)
#define OFF_CS (2 * BUF_B)
#define SMEM_SZ (OFF_CS + 512)
// gemm2 geometry: 2 buffers x 4 planes x 8KB
#define B2     32768
#define P_AH   0
#define P_AL   8192
#define P_BH   16384
#define P_BL   24576
#define OFF_MB (2 * B2)
#define SMEM2  (OFF_MB + 32)

__device__ __forceinline__ uint32_t smem_u32(const void* p) {
    uint32_t a;
    asm("{ .reg .u64 t; cvta.to.shared.u64 t, %1; cvt.u32.u64 %0, t; }"
        : "=r"(a) : "l"(p));
    return a;
}
__device__ __forceinline__ void cpa(uint32_t d, const void* s) {
    asm volatile("cp.async.cg.shared.global [%0], [%1], 16;"
                 :: "r"(d), "l"(__cvta_generic_to_global(s)));
}
#define CP_COMMIT() asm volatile("cp.async.commit_group;" ::: "memory")
#define CP_WAIT(n)  asm volatile("cp.async.wait_group %0;" :: "n"(n) : "memory")
__device__ __forceinline__ void bulk_ld(uint32_t sdst, const void* gsrc,
                                        uint32_t bytes, uint32_t mbar) {
    asm volatile(
        "cp.async.bulk.shared::cluster.global.mbarrier::complete_tx::bytes "
        "[%0], [%1], %2, [%3];"
        :: "r"(sdst), "l"(__cvta_generic_to_global(gsrc)), "r"(bytes), "r"(mbar)
        : "memory");
}
#define MBAR_INIT(mb, n) \
    asm volatile("mbarrier.init.shared.b64 [%0], %1;" \
                 :: "r"((uint32_t)(mb)), "r"((uint32_t)(n)) : "memory")
#define MBAR_EXPECT(mb, tx) \
    asm volatile("mbarrier.arrive.expect_tx.shared.b64 _, [%0], %1;" \
                 :: "r"((uint32_t)(mb)), "r"((uint32_t)(tx)) : "memory")
#define MBAR_WAIT(mb, ph) do {                                                        \
    uint32_t _m = (uint32_t)(mb), _p = (uint32_t)(ph), _d;                            \
    asm volatile("{\n\t.reg .pred p;\n\t"                                             \
        "mbarrier.try_wait.parity.acquire.cta.shared::cta.b64 p, [%1], %2;\n\t"       \
        "selp.b32 %0, 1, 0, p;\n\t}" : "=r"(_d) : "r"(_m), "r"(_p) : "memory");       \
    if (!_d) {                                                                        \
        asm volatile("{\n\t.reg .pred P1;\n\tWL_%=:\n\t"                              \
            "mbarrier.try_wait.parity.acquire.cta.shared::cta.b64 P1, [%0], %1, 0x989680;\n\t" \
            "@P1 bra.uni WD_%=;\n\tbra.uni WL_%=;\n\tWD_%=:\n\t}"                     \
            :: "r"(_m), "r"(_p) : "memory");                                          \
    }                                                                                 \
} while (0)

__device__ __forceinline__ void ldsm4(uint32_t* r, uint32_t a) {
    asm volatile("ldmatrix.sync.aligned.m8n8.x4.shared.b16 {%0,%1,%2,%3}, [%4];"
                 : "=r"(r[0]), "=r"(r[1]), "=r"(r[2]), "=r"(r[3]) : "r"(a));
}
__device__ __forceinline__ void mma16816(float* d, const uint32_t* a, const uint32_t* b) {
    asm volatile("mma.sync.aligned.m16n8k16.row.col.f32.bf16.bf16.f32 "
                 "{%0,%1,%2,%3}, {%4,%5,%6,%7}, {%8,%9}, {%0,%1,%2,%3};"
                 : "+f"(d[0]), "+f"(d[1]), "+f"(d[2]), "+f"(d[3])
                 : "r"(a[0]), "r"(a[1]), "r"(a[2]), "r"(a[3]),
                   "r"(b[0]), "r"(b[1]));
}
__device__ __forceinline__ uint32_t cvt2(float a, float b) {
    uint32_t d;
    asm("cvt.rn.bf16x2.f32 %0, %1, %2;" : "=r"(d) : "f"(a), "f"(b));
    return d;
}
// swizzled in-block offset (row 0..127, colb 0..63)
__device__ __forceinline__ uint32_t swz(int row, int colb) {
    return (uint32_t)(row * 64 + colb) ^ (uint32_t)((row & 14) << 3);
}

// ---- gemm1 loader / mma (R16, unchanged) ----------------------------------
__device__ __forceinline__ void load_chunk(
    uint32_t buf, const __nv_bfloat16* ah, const __nv_bfloat16* al,
    const __nv_bfloat16* bh, const __nv_bfloat16* bl, int tid)
{
#pragma unroll
    for (int r = 0; r < 2; r++) {
        int idx = tid + 256 * r;
        int row = idx >> 2, seg = idx & 3;
        uint32_t d = buf + row * TSTR + seg * 16;
        size_t s = (size_t)row * CD + seg * 8;
        cpa(d + OFF_AH, ah + s);
        cpa(d + OFF_AL, al + s);
        cpa(d + OFF_BH, bh + s);
        cpa(d + OFF_BL, bl + s);
    }
}
__device__ __forceinline__ void mma_chunk(
    float acc[4][4][4], uint32_t buf, int wm, int wn, int lane)
{
    uint32_t a_base = buf + (uint32_t)(wm * 64 + (lane & 15)) * TSTR + ((lane >> 4) << 4);
    uint32_t b_base = buf + (uint32_t)(wn * 32 + ((lane >> 4) << 3) + (lane & 7)) * TSTR
                    + (((lane >> 3) & 1) << 4);
#pragma unroll
    for (int ks = 0; ks < 2; ks++) {
        uint32_t ah[4][4], al[4][4], bhf[4][2], blf[4][2];
#pragma unroll
        for (int i = 0; i < 4; i++) {
            ldsm4(ah[i], a_base + OFF_AH + i * 16 * TSTR + ks * 32);
            ldsm4(al[i], a_base + OFF_AL + i * 16 * TSTR + ks * 32);
        }
#pragma unroll
        for (int jj = 0; jj < 2; jj++) {
            uint32_t t[4];
            ldsm4(t, b_base + OFF_BH + jj * 16 * TSTR + ks * 32);
            bhf[2 * jj][0] = t[0]; bhf[2 * jj][1] = t[1];
            bhf[2 * jj + 1][0] = t[2]; bhf[2 * jj + 1][1] = t[3];
            ldsm4(t, b_base + OFF_BL + jj * 16 * TSTR + ks * 32);
            blf[2 * jj][0] = t[0]; blf[2 * jj][1] = t[1];
            blf[2 * jj + 1][0] = t[2]; blf[2 * jj + 1][1] = t[3];
        }
#pragma unroll
        for (int i = 0; i < 4; i++)
#pragma unroll
            for (int j = 0; j < 4; j++) {
                mma16816(acc[i][j], ah[i], bhf[j]);
                mma16816(acc[i][j], ah[i], blf[j]);
                mma16816(acc[i][j], al[i], bhf[j]);
            }
    }
}

// ---- preps ----------------------------------------------------------------
__global__ void splitT_kernel(const float* __restrict__ Q,
                              const float* __restrict__ K) {
    __shared__ float tbuf[64][33];
    int z = blockIdx.z;
    int sel = z >= BH, bh = z & (BH - 1);
    int c0 = blockIdx.y * 64, l0 = blockIdx.x * 32;
    int tx = threadIdx.x, ty = threadIdx.y;
    const float* Xb = (sel ? K : Q) + ((size_t)bh * CD + c0) * LL + l0;
#pragma unroll
    for (int i = 0; i < 8; i++)
        tbuf[ty + 8 * i][tx] = Xb[(size_t)(ty + 8 * i) * LL + tx];
    if (!sel && blockIdx.y == 0 && ty == 0) g_r[bh * LL + l0 + tx] = 0.0f;
    __syncthreads();
    uint32_t* Dh = (uint32_t*)((sel ? g_Kh : g_Qh)
                   + ((size_t)bh * LL + l0) * CD + c0);
    uint32_t* Dl = (uint32_t*)((sel ? g_Kl : g_Ql)
                   + ((size_t)bh * LL + l0) * CD + c0);
#pragma unroll
    for (int i = 0; i < 4; i++) {
        int row = ty + 8 * i;
        float a = tbuf[2 * tx][row];
        float b = tbuf[2 * tx + 1][row];
        uint32_t h = cvt2(b, a);
        float fa = __uint_as_float(h << 16);
        float fb = __uint_as_float(h & 0xFFFF0000u);
        uint32_t l = cvt2(b - fb, a - fa);
        Dh[(size_t)row * (CD / 2) + tx] = h;
        Dl[(size_t)row * (CD / 2) + tx] = l;
    }
}

// V/r -> blocked-swizzled bf16 hi/lo. grid (CD, BH), 256 threads.
__global__ void vprep_kernel(const float* __restrict__ V) {
    int c = blockIdx.x, bh = blockIdx.y;
    size_t base = ((size_t)bh * CD + c) * LL;
    const float4* v4 = (const float4*)(V + base);
    const float4* r4 = (const float4*)(g_r + bh * LL);
    int t = threadIdx.x;
#pragma unroll
    for (int it = 0; it < 2; it++) {
        int u = t + 256 * it;                 // k = 4u
        float4 v = v4[u], r = r4[u];
        float a0 = __fdividef(v.x, r.x), a1 = __fdividef(v.y, r.y);
        float a2 = __fdividef(v.z, r.z), a3 = __fdividef(v.w, r.w);
        uint32_t h01 = cvt2(a1, a0), h23 = cvt2(a3, a2);
        float f0 = __uint_as_float(h01 << 16);
        float f1 = __uint_as_float(h01 & 0xFFFF0000u);
        float f2 = __uint_as_float(h23 << 16);
        float f3 = __uint_as_float(h23 & 0xFFFF0000u);
        uint32_t l01 = cvt2(a1 - f1, a0 - f0);
        uint32_t l23 = cvt2(a3 - f3, a2 - f2);
        uint32_t o = swz(c, (u & 7) * 8);
        char* Dh = (char*)g_Vh + ((size_t)(bh * 64 + (u >> 3))) * BLK + o;
        char* Dl = (char*)g_Vl + ((size_t)(bh * 64 + (u >> 3))) * BLK + o;
        *(uint32_t*)Dh = h01; *(uint32_t*)(Dh + 4) = h23;
        *(uint32_t*)Dl = l01; *(uint32_t*)(Dl + 4) = l23;
    }
}

// ---- GEMM1: as R16, E staged into swizzled blocks, contiguous store -------
__global__ __launch_bounds__(256, 2) void gemm1_kernel() {
    extern __shared__ __align__(128) char sm[];
    const uint32_t sb = smem_u32(sm);
    const int tid = threadIdx.x, wid = tid >> 5, lane = tid & 31;
    const int wm = wid & 1, wn = wid >> 1;
    const int qb = blockIdx.x, kb = blockIdx.y, bh = blockIdx.z;
    const int q0 = qb * 128, k0 = kb * 128;

    {
        int flat = blockIdx.x + 16 * (blockIdx.y + 16 * blockIdx.z);
        if (flat >= 148 && flat < 296) {
            long long t0 = clock64();
            while (clock64() - t0 < 11000) {}
        }
    }

    float* cs = (float*)(sm + OFF_CS);
    if (tid < 128) cs[tid] = 0.0f;

    const __nv_bfloat16* Qh = g_Qh + ((size_t)bh * LL + q0) * CD;
    const __nv_bfloat16* Ql = g_Ql + ((size_t)bh * LL + q0) * CD;
    const __nv_bfloat16* Kh = g_Kh + ((size_t)bh * LL + k0) * CD;
    const __nv_bfloat16* Kl = g_Kl + ((size_t)bh * LL + k0) * CD;

    load_chunk(sb, Qh, Ql, Kh, Kl, tid);
    CP_COMMIT();

    float acc[4][4][4];
#pragma unroll
    for (int i = 0; i < 4; i++)
#pragma unroll
        for (int j = 0; j < 4; j++)
#pragma unroll
            for (int v = 0; v < 4; v++) acc[i][j][v] = 0.0f;

#pragma unroll 1
    for (int ck = 0; ck < 4; ck++) {
        CP_WAIT(0);
        __syncthreads();
        if (ck + 1 < 4) {
            int off = (ck + 1) * 32;
            load_chunk(sb + ((ck + 1) & 1) * BUF_B, Qh + off, Ql + off,
                       Kh + off, Kl + off, tid);
            CP_COMMIT();
        }
        mma_chunk(acc, sb + (ck & 1) * BUF_B, wm, wn, lane);
    }
    __syncthreads();

#pragma unroll
    for (int i = 0; i < 4; i++)
#pragma unroll
        for (int j = 0; j < 4; j++)
#pragma unroll
            for (int v = 0; v < 4; v++) acc[i][j][v] = __expf(acc[i][j][v]);

#pragma unroll
    for (int j = 0; j < 4; j++) {
        float p0 = 0.0f, p1 = 0.0f;
#pragma unroll
        for (int i = 0; i < 4; i++) {
            p0 += acc[i][j][0] + acc[i][j][2];
            p1 += acc[i][j][1] + acc[i][j][3];
        }
        p0 += __shfl_xor_sync(0xffffffffu, p0, 4);
        p1 += __shfl_xor_sync(0xffffffffu, p1, 4);
        p0 += __shfl_xor_sync(0xffffffffu, p0, 8);
        p1 += __shfl_xor_sync(0xffffffffu, p1, 8);
        p0 += __shfl_xor_sync(0xffffffffu, p0, 16);
        p1 += __shfl_xor_sync(0xffffffffu, p1, 16);
        if ((lane >> 2) == 0) {
            int c = wn * 32 + j * 8 + (lane & 3) * 2;
            atomicAdd(&cs[c], p0);
            atomicAdd(&cs[c + 1], p1);
        }
    }

    // stage into swizzled blocks: Eh at sm[wn*8K], El at +32K
#pragma unroll
    for (int i = 0; i < 4; i++)
#pragma unroll
        for (int j = 0; j < 4; j++) {
            int r  = wm * 64 + i * 16 + (lane >> 2);
            int cb = j * 16 + (lane & 3) * 4;
            float a0 = acc[i][j][0], a1 = acc[i][j][1];
            float a2 = acc[i][j][2], a3 = acc[i][j][3];
            uint32_t hp01 = cvt2(a1, a0);
            uint32_t hp23 = cvt2(a3, a2);
            float f0 = __uint_as_float(hp01 << 16);
            float f1 = __uint_as_float(hp01 & 0xFFFF0000u);
            float f2 = __uint_as_float(hp23 << 16);
            float f3 = __uint_as_float(hp23 & 0xFFFF0000u);
            uint32_t lp01 = cvt2(a1 - f1, a0 - f0);
            uint32_t lp23 = cvt2(a3 - f3, a2 - f2);
            uint32_t o0 = wn * BLK + swz(r, cb);
            uint32_t o8 = wn * BLK + swz(r + 8, cb);
            *(uint32_t*)(sm + o0) = hp01;
            *(uint32_t*)(sm + o8) = hp23;
            *(uint32_t*)(sm + 32768 + o0) = lp01;
            *(uint32_t*)(sm + 32768 + o8) = lp23;
        }
    __syncthreads();

    if (tid < 128) atomicAdd(&g_r[bh * LL + k0 + tid], cs[tid]);

    // contiguous 32KB per plane: blocks ck = kb*4 .. kb*4+3
    size_t ebase = ((size_t)((bh * 16 + qb) * 64 + kb * 4)) * BLK;
    uint4* EhD = (uint4*)((char*)g_Eh + ebase);
    uint4* ElD = (uint4*)((char*)g_El + ebase);
    const uint4* S = (const uint4*)sm;
#pragma unroll
    for (int it = 0; it < 8; it++) {
        int idx = tid + 256 * it;            // 0..2047 x 16B = 32KB
        EhD[idx] = S[idx];
        ElD[idx] = S[2048 + idx];
    }
}

// ---- GEMM2: bulk-loaded blocked chunks ------------------------------------
__global__ __launch_bounds__(256, 2) void gemm2_kernel(float* __restrict__ Out) {
    extern __shared__ __align__(128) char sm[];
    const uint32_t sb = smem_u32(sm);
    const int tid = threadIdx.x, wid = tid >> 5, lane = tid & 31;
    const int wm = wid & 1, wn = wid >> 1;
    const int qb = blockIdx.x, bh = blockIdx.y;

    const uint32_t mb0 = sb + OFF_MB, mb1 = sb + OFF_MB + 8;
    if (tid == 0) { MBAR_INIT(mb0, 1); MBAR_INIT(mb1, 1); }
    __syncthreads();

    auto issue = [&](int ck) {
        uint32_t buf = sb + (ck & 1) * B2;
        uint32_t mb = (ck & 1) ? mb1 : mb0;
        size_t vo = ((size_t)(bh * 64 + ck)) * BLK;
        size_t eo = ((size_t)((bh * 16 + qb) * 64 + ck)) * BLK;
        MBAR_EXPECT(mb, 4 * BLK);
        bulk_ld(buf + P_AH, (char*)g_Vh + vo, BLK, mb);
        bulk_ld(buf + P_AL, (char*)g_Vl + vo, BLK, mb);
        bulk_ld(buf + P_BH, (char*)g_Eh + eo, BLK, mb);
        bulk_ld(buf + P_BL, (char*)g_El + eo, BLK, mb);
    };
    if (tid == 0) issue(0);

    float acc[4][4][4];
#pragma unroll
    for (int i = 0; i < 4; i++)
#pragma unroll
        for (int j = 0; j < 4; j++)
#pragma unroll
            for (int v = 0; v < 4; v++) acc[i][j][v] = 0.0f;

    const int a_row = wm * 64 + (lane & 15);
    const uint32_t a_lin = (uint32_t)(a_row * 64) + ((lane >> 4) << 4);
    const uint32_t TA = (uint32_t)((a_row & 14) << 3);
    const int b_row = wn * 32 + ((lane >> 4) << 3) + (lane & 7);
    const uint32_t b_lin = (uint32_t)(b_row * 64) + (((lane >> 3) & 1) << 4);
    const uint32_t TB = (uint32_t)((b_row & 14) << 3);

#pragma unroll 1
    for (int ck = 0; ck < 64; ck++) {
        __syncthreads();                      // mma(ck-1) done -> buffer free
        if (tid == 0 && ck + 1 < 64) issue(ck + 1);
        MBAR_WAIT((ck & 1) ? mb1 : mb0, (ck >> 1) & 1);
        uint32_t buf = sb + (ck & 1) * B2;
#pragma unroll
        for (int ks = 0; ks < 2; ks++) {
            uint32_t ab = buf + ((a_lin + ks * 32) ^ TA);
            uint32_t bb = buf + ((b_lin + ks * 32) ^ TB);
            uint32_t ah[4][4], al[4][4], bhf[4][2], blf[4][2];
#pragma unroll
            for (int i = 0; i < 4; i++) {
                ldsm4(ah[i], ab + P_AH + i * 1024);
                ldsm4(al[i], ab + P_AL + i * 1024);
            }
#pragma unroll
            for (int jj = 0; jj < 2; jj++) {
                uint32_t t[4];
                ldsm4(t, bb + P_BH + jj * 1024);
                bhf[2 * jj][0] = t[0]; bhf[2 * jj][1] = t[1];
                bhf[2 * jj + 1][0] = t[2]; bhf[2 * jj + 1][1] = t[3];
                ldsm4(t, bb + P_BL + jj * 1024);
                blf[2 * jj][0] = t[0]; blf[2 * jj][1] = t[1];
                blf[2 * jj + 1][0] = t[2]; blf[2 * jj + 1][1] = t[3];
            }
#pragma unroll
            for (int i = 0; i < 4; i++)
#pragma unroll
                for (int j = 0; j < 4; j++) {
                    mma16816(acc[i][j], ah[i], bhf[j]);
                    mma16816(acc[i][j], ah[i], blf[j]);
                    mma16816(acc[i][j], al[i], bhf[j]);
                }
        }
    }

#pragma unroll
    for (int i = 0; i < 4; i++)
#pragma unroll
        for (int j = 0; j < 4; j++) {
            int r  = wm * 64 + i * 16 + (lane >> 2);
            int qc = qb * 128 + wn * 32 + j * 8 + (lane & 3) * 2;
            float* ob = Out + ((size_t)bh * CD + r) * LL + qc;
            *(float2*)ob = make_float2(acc[i][j][0], acc[i][j][1]);
            *(float2*)(ob + 8 * LL) = make_float2(acc[i][j][2], acc[i][j][3]);
        }
}

// ---------------------------------------------------------------------------
extern "C" void kernel_launch(void* const* d_in, const int* in_sizes, int n_in,
                              void* d_out, int out_size)
{
    const float* q = (const float*)d_in[0];
    const float* k = (const float*)d_in[1];
    const float* v = (const float*)d_in[2];
    float* out = (float*)d_out;

    cudaFuncSetAttribute(gemm1_kernel, cudaFuncAttributeMaxDynamicSharedMemorySize, SMEM_SZ);
    cudaFuncSetAttribute(gemm2_kernel, cudaFuncAttributeMaxDynamicSharedMemorySize, SMEM2);

    splitT_kernel<<<dim3(LL / 32, CD / 64, 2 * BH), dim3(32, 8)>>>(q, k);
    gemm1_kernel<<<dim3(16, 16, BH), 256, SMEM_SZ>>>();
    vprep_kernel<<<dim3(CD, BH), 256>>>(v);
    gemm2_kernel<<<dim3(16, BH), 256, SMEM2>>>(out);
}